// round 11
// baseline (speedup 1.0000x reference)
#include <cuda_runtime.h>
#include <stdint.h>

#define NUM_CLASSES 10000
#define FEATURE_DIM 2048
#define BATCH 512
#define TPB 256
#define NTOT ((size_t)NUM_CLASSES * FEATURE_DIM)
#define COPY_GRID (148 * 8)
#define GRID_TOT (BATCH + COPY_GRID)
#define BM_WORDS ((NUM_CLASSES + 31) / 32)   // 313
// ALPHA = 0.5 exactly -> powers of two via ldexpf

__device__ float g_part[BATCH];   // per-owner-slot loss partials (all written every launch)
__device__ int   g_ctr = 0;       // completion counter; reducer resets to 0

// ---------------------------------------------------------------------------
// Single fused kernel.
//  blocks [0, BATCH): owner candidates. Block b handles label s_lab[b] iff b is
//    the minimum batch index with that label; computes closed-form sequential
//    EMA  new_c = 2^-k*c + sum_r 2^-(k-r)*f_r  (batch order, ALPHA=0.5) and
//    its loss partial (vs ORIGINAL center row). Non-owners write partial 0.
//  blocks [BATCH, GRID_TOT): copy of all UNMATCHED rows (smem bitmap).
//  Tail: threadfence-reduction — last finishing block sums the 512 partials in
//  fixed order and writes out[0]; resets g_ctr (graph-replay safe, deterministic).
// MODE 0: dst rows 16B-aligned; MODE 1: dst base == 4 (mod 16); MODE 2 scalar.
// ---------------------------------------------------------------------------
template <int MODE>
__global__ void __launch_bounds__(TPB)
fused_kernel(const float* __restrict__ features,
             const float* __restrict__ centers,
             float* __restrict__ out_centers,
             float* __restrict__ loss_out,
             const int* __restrict__ labels_words) {
    __shared__ int          s_lab[BATCH];
    __shared__ int          s_not64;
    __shared__ unsigned int s_bm[BM_WORDS];
    __shared__ int          s_match[BATCH];
    __shared__ float        s_w[BATCH];
    __shared__ int          s_cnt;
    __shared__ float        s_red[TPB / 32];
    __shared__ int          s_last;

    const int tid = threadIdx.x;

    // ---- per-block label decode (int64 vs int32 probe) ----
    // Each thread covers indices tid and tid+TPB; issue all 4 loads up front.
    int i0 = tid, i1 = tid + TPB;
    int w0lo = __ldg(labels_words + 2 * i0);
    int w0hi = __ldg(labels_words + 2 * i0 + 1);
    int w1lo = __ldg(labels_words + 2 * i1);
    int w1hi = __ldg(labels_words + 2 * i1 + 1);
    if (tid == 0) { s_not64 = 0; s_cnt = 0; }
    __syncthreads();
    if (w0hi != 0 || w0lo < 0 || w0lo >= NUM_CLASSES ||
        w1hi != 0 || w1lo < 0 || w1lo >= NUM_CLASSES)
        s_not64 = 1;                                   // benign race
    __syncthreads();
    if (s_not64) {
        s_lab[i0] = __ldg(labels_words + i0);
        s_lab[i1] = __ldg(labels_words + i1);
    } else {
        s_lab[i0] = w0lo;
        s_lab[i1] = w1lo;
    }
    __syncthreads();

    if (blockIdx.x < BATCH) {
        // ---------------- owner-candidate block ----------------
        const int b = blockIdx.x;
        const int l = s_lab[b];
        for (int j = tid; j < BATCH; j += TPB)
            if (s_lab[j] == l) s_match[atomicAdd(&s_cnt, 1)] = j;
        __syncthreads();
        const int k = s_cnt;
        if (tid == 0) {   // batch order + EMA weights
            for (int a = 1; a < k; a++) {
                int v = s_match[a], c = a - 1;
                while (c >= 0 && s_match[c] > v) { s_match[c + 1] = s_match[c]; c--; }
                s_match[c + 1] = v;
            }
            for (int r = 0; r < k; r++) s_w[r] = ldexpf(1.0f, -(k - r));
        }
        __syncthreads();

        const bool owner = (s_match[0] == b);   // uniform across block
        float total = 0.0f;
        if (owner) {
            const float* crow = centers     + (size_t)l * FEATURE_DIM;
            float*       orow = out_centers + (size_t)l * FEATURE_DIM;
            const float  decay = ldexpf(1.0f, -k);
            float acc = 0.0f;
            #pragma unroll
            for (int s = 0; s < FEATURE_DIM / TPB; s++) {
                int c = tid + s * TPB;
                float cv = __ldg(crow + c);
                float nv = cv * decay;
                for (int r = 0; r < k; r++) {
                    float f = __ldg(features + (size_t)s_match[r] * FEATURE_DIM + c);
                    nv = fmaf(s_w[r], f, nv);
                    float d = f - cv;            // loss vs ORIGINAL center
                    acc = fmaf(d, d, acc);
                }
                orow[c] = nv;
            }
            #pragma unroll
            for (int o = 16; o; o >>= 1) acc += __shfl_xor_sync(0xffffffffu, acc, o);
            if ((tid & 31) == 0) s_red[tid >> 5] = acc;
            __syncthreads();
            if (tid == 0) {
                float a2 = 0.0f;
                #pragma unroll
                for (int w = 0; w < TPB / 32; w++) a2 += s_red[w];
                total = a2 * (1.0f / ((float)BATCH * (float)FEATURE_DIM));
            }
        }
        if (tid == 0) g_part[b] = owner ? total : 0.0f;
    } else {
        // ---------------- copy block ----------------
        for (int i = tid; i < BM_WORDS; i += TPB) s_bm[i] = 0u;
        __syncthreads();
        for (int i = tid; i < BATCH; i += TPB) {
            int l = s_lab[i];
            atomicOr(&s_bm[l >> 5], 1u << (l & 31));
        }
        __syncthreads();

        const int cid  = blockIdx.x - BATCH;
        const int lane = tid & 31;

        for (int r = cid; r < NUM_CLASSES; r += COPY_GRID) {
            if ((s_bm[r >> 5] >> (r & 31)) & 1u) continue;
            const float* srow = centers     + (size_t)r * FEATURE_DIM;
            float*       drow = out_centers + (size_t)r * FEATURE_DIM;

            if (MODE == 0) {
                const float4* s4 = (const float4*)srow;
                float4*       d4 = (float4*)drow;
                #pragma unroll
                for (int s = 0; s < (FEATURE_DIM / 4) / TPB; s++) {
                    int j = tid + s * TPB;
                    d4[j] = __ldg(s4 + j);
                }
            } else if (MODE == 1) {
                // drow == 4 (mod 16): quads [3+4j..6+4j] aligned, j in [0,511).
                if (tid < 3)  drow[tid] = __ldg(srow + tid);
                if (tid == 3) drow[FEATURE_DIM - 1] = __ldg(srow + FEATURE_DIM - 1);
                #pragma unroll
                for (int s = 0; s < 2; s++) {
                    int  j   = tid + s * TPB;
                    bool act = j < (FEATURE_DIM / 4) - 1;
                    int  jc  = act ? j : (FEATURE_DIM / 4) - 2;
                    float4 q = __ldg((const float4*)srow + jc + 1);
                    float  w = __shfl_up_sync(0xffffffffu, q.w, 1);
                    if (lane == 0) w = __ldg(srow + 4 * jc + 3);
                    if (act)
                        *(float4*)(drow + 3 + 4 * j) = make_float4(w, q.x, q.y, q.z);
                }
            } else {
                #pragma unroll
                for (int s = 0; s < FEATURE_DIM / TPB; s++) {
                    int c = tid + s * TPB;
                    drow[c] = __ldg(srow + c);
                }
            }
        }
    }

    // ---------------- tail: last-block loss reduction ----------------
    __threadfence();
    __syncthreads();
    if (tid == 0) {
        int old = atomicAdd(&g_ctr, 1);
        s_last = (old == GRID_TOT - 1) ? 1 : 0;
    }
    __syncthreads();
    if (s_last) {
        float a = 0.0f;
        for (int i = tid; i < BATCH; i += TPB)
            a += ((volatile float*)g_part)[i];
        #pragma unroll
        for (int o = 16; o; o >>= 1) a += __shfl_xor_sync(0xffffffffu, a, o);
        if ((tid & 31) == 0) s_red[tid >> 5] = a;
        __syncthreads();
        if (tid == 0) {
            float t = 0.0f;
            #pragma unroll
            for (int w = 0; w < TPB / 32; w++) t += s_red[w];
            loss_out[0] = t;
            g_ctr = 0;                       // reset for next launch/replay
        }
    }
}

extern "C" void kernel_launch(void* const* d_in, const int* in_sizes, int n_in,
                              void* d_out, int out_size) {
    const float* features = (const float*)d_in[0];
    const int*   labels_w = (const int*)d_in[1];
    const float* centers  = (const float*)d_in[2];

    float* out = (float*)d_out;
    float* out_centers = out + ((size_t)out_size - NTOT);

    uintptr_t a = (uintptr_t)out_centers;
    if ((a & 15) == 0)
        fused_kernel<0><<<GRID_TOT, TPB>>>(features, centers, out_centers, out, labels_w);
    else if ((a & 15) == 4)
        fused_kernel<1><<<GRID_TOT, TPB>>>(features, centers, out_centers, out, labels_w);
    else
        fused_kernel<2><<<GRID_TOT, TPB>>>(features, centers, out_centers, out, labels_w);
}